// round 4
// baseline (speedup 1.0000x reference)
#include <cuda_runtime.h>
#include <cuda_bf16.h>
#include <cstdint>

// SparseBoundaryContent: x [16, 512, 64] f32.
// boundary(i,j) = (x[i]+x[j])/2 on masked cells, content(i,j) = max(x[i..j])
// on masked cells, 0 elsewhere.
// Output layout (flat f32): [boundary B*D*N*N][content B*D*N*N][mask B*N*N].
//
// Pattern is compile-time: mask as per-row 64-bit bitmasks in __constant__,
// masked-cell RMQ descriptors as a __device__ table. Masking is done with
// selects (not multiplies), so the content scratch tile needs no zero-fill.

#define NB 16
#define ND 512
#define NN 64
#define NCELLS 4096          // 64*64 cells per (b,d) row
#define NMASKED 1104         // masked cells per tile (incl. diagonal)

constexpr bool cell_mask_ct(int i, int j) {
    int d = j - i;
    if (d < 0)  return false;
    if (d <= 15) return true;                              // stride-1 offsets 0..15
    if (d <= 31) return (d & 1) && !(i & 1);               // stride-2: odd 17..31, i even
    return (d >= 35) && ((d & 3) == 3) && !(i & 3);        // stride-4: 35,39,..,63, i%4==0
}

struct RowMasks { uint64_t rm[NN]; };
constexpr RowMasks gen_rowmasks() {
    RowMasks r{};
    for (int i = 0; i < NN; i++) {
        uint64_t m = 0;
        for (int j = 0; j < NN; j++)
            if (cell_mask_ct(i, j)) m |= (uint64_t)1 << j;
        r.rm[i] = m;
    }
    return r;
}
__constant__ constexpr RowMasks g_rm = gen_rowmasks();

struct Meta { unsigned int m[NMASKED]; };
constexpr Meta gen_meta() {
    Meta t{};
    int cnt = 0;
    for (int i = 0; i < NN; i++) {
        for (int j = 0; j < NN; j++) {
            if (!cell_mask_ct(i, j)) continue;
            int len = j - i + 1;
            int k = 0;
            while ((1 << (k + 1)) <= len) k++;             // floor(log2(len))
            int ri = j + 1 - (1 << k);
            unsigned offL = (unsigned)(k * NN + i);
            unsigned offR = (unsigned)(k * NN + ri);
            t.m[cnt++] = (unsigned)(i * NN + j) | (offL << 12) | (offR << 21);
        }
    }
    return t;
}
__device__ constexpr Meta g_meta = gen_meta();

__global__ void __launch_bounds__(256)
sbc_kernel(const float* __restrict__ x,
           float* __restrict__ boundary,
           float* __restrict__ content,
           float* __restrict__ mask_out)
{
    __shared__ float Mf[7 * NN];       // sparse max table; Mf[0..63] = x row
    __shared__ float ctile[NCELLS];    // content at masked cells; rest UNINITIALIZED

    const int bd  = blockIdx.x;        // bd = b*ND + d
    const int tid = threadIdx.x;

    if (tid < NN) Mf[tid] = x[(size_t)bd * NN + tid];
    __syncthreads();

    // Sparse max table: Mf[k*64+i] = max x[i .. min(i+2^k-1, 63)]
    #pragma unroll
    for (int k = 1; k < 7; k++) {
        if (tid < NN) {
            int o = tid + (1 << (k - 1));
            if (o > NN - 1) o = NN - 1;
            Mf[k * NN + tid] = fmaxf(Mf[(k - 1) * NN + tid], Mf[(k - 1) * NN + o]);
        }
        __syncthreads();
    }

    // Phase 1: content at the 1104 masked cells (one O(1) RMQ each).
    #pragma unroll
    for (int p = 0; p < 5; p++) {
        int idx = p * 256 + tid;
        if (idx < NMASKED) {
            unsigned m = g_meta.m[idx];
            ctile[m & 4095u] = fmaxf(Mf[(m >> 12) & 511u], Mf[(m >> 21) & 511u]);
        }
    }
    __syncthreads();

    float* bptr = boundary + (size_t)bd * NCELLS;
    float* cptr = content  + (size_t)bd * NCELLS;

    // j-block is pass-invariant: c0 & 63 == (tid & 15) * 4 for all passes.
    const int j0 = (tid & 15) * 4;
    const float4 xj = *reinterpret_cast<const float4*>(&Mf[j0]);

    // Phase 2: pure store stream. 4 cells/thread/pass, select-masked.
    #pragma unroll
    for (int p = 0; p < 4; p++) {
        const int g  = p * 256 + tid;
        const int c0 = g * 4;
        const int i  = g >> 4;
        const float xih = 0.5f * Mf[i];
        const unsigned rmv = (unsigned)(g_rm.rm[i] >> j0);   // bits 0..3 = cells
        const float4 ct = *reinterpret_cast<const float4*>(&ctile[c0]);

        float4 bo, co;
        bo.x = (rmv & 1u) ? fmaf(0.5f, xj.x, xih) : 0.0f;
        bo.y = (rmv & 2u) ? fmaf(0.5f, xj.y, xih) : 0.0f;
        bo.z = (rmv & 4u) ? fmaf(0.5f, xj.z, xih) : 0.0f;
        bo.w = (rmv & 8u) ? fmaf(0.5f, xj.w, xih) : 0.0f;
        co.x = (rmv & 1u) ? ct.x : 0.0f;
        co.y = (rmv & 2u) ? ct.y : 0.0f;
        co.z = (rmv & 4u) ? ct.z : 0.0f;
        co.w = (rmv & 8u) ? ct.w : 0.0f;

        *reinterpret_cast<float4*>(bptr + c0) = bo;
        *reinterpret_cast<float4*>(cptr + c0) = co;
    }

    // The 16 CTAs with d == 0 emit the broadcast mask slice for batch b.
    if ((bd & (ND - 1)) == 0) {
        float* mp = mask_out + (size_t)(bd >> 9) * NCELLS;
        #pragma unroll
        for (int p = 0; p < 4; p++) {
            const int g  = p * 256 + tid;
            const int c0 = g * 4;
            const int i  = g >> 4;
            const unsigned rmv = (unsigned)(g_rm.rm[i] >> j0);
            float4 mo;
            mo.x = (rmv & 1u) ? 1.0f : 0.0f;
            mo.y = (rmv & 2u) ? 1.0f : 0.0f;
            mo.z = (rmv & 4u) ? 1.0f : 0.0f;
            mo.w = (rmv & 8u) ? 1.0f : 0.0f;
            *reinterpret_cast<float4*>(mp + c0) = mo;
        }
    }
}

extern "C" void kernel_launch(void* const* d_in, const int* in_sizes, int n_in,
                              void* d_out, int out_size) {
    const float* x = (const float*)d_in[0];
    float* out = (float*)d_out;

    const size_t map_elems = (size_t)NB * ND * NN * NN;   // 33,554,432
    float* boundary = out;
    float* content  = out + map_elems;
    float* mask_out = out + 2 * map_elems;

    sbc_kernel<<<NB * ND, 256>>>(x, boundary, content, mask_out);
}

// round 5
// speedup vs baseline: 1.4347x; 1.4347x over previous
#include <cuda_runtime.h>
#include <cuda_bf16.h>

// SparseBoundaryContent: x [16, 512, 64] f32.
// boundary(i,j) = (x[i]+x[j])/2 on masked cells, content(i,j) = max(x[i..j])
// on masked cells, 0 elsewhere.
// Output layout (flat f32): [boundary B*D*N*N][content B*D*N*N][mask B*N*N].
//
// R4: R2 structure (float mask table, zeroed ctile, multiply-masking) with
// 2 rows per CTA to amortize mask loads / barriers / phase-1, and xj hoisted.

#define NB 16
#define ND 512
#define NN 64
#define NCELLS 4096          // 64*64 cells per (b,d) row
#define NMASKED 1104         // masked cells per tile (incl. diagonal)
#define RPC 2                // (b,d) rows per CTA

constexpr bool cell_mask_ct(int i, int j) {
    int d = j - i;
    if (d < 0)  return false;
    if (d <= 15) return true;                              // stride-1 offsets 0..15
    if (d <= 31) return (d & 1) && !(i & 1);               // stride-2: odd 17..31, i even
    return (d >= 35) && ((d & 3) == 3) && !(i & 3);        // stride-4: 35,39,..,63, i%4==0
}

struct MaskTab { float m[NCELLS]; };
constexpr MaskTab gen_mask() {
    MaskTab t{};
    for (int i = 0; i < NN; i++)
        for (int j = 0; j < NN; j++)
            t.m[i * NN + j] = cell_mask_ct(i, j) ? 1.0f : 0.0f;
    return t;
}
__device__ constexpr MaskTab g_mask = gen_mask();

struct Meta { unsigned int m[NMASKED]; };
constexpr Meta gen_meta() {
    Meta t{};
    int cnt = 0;
    for (int i = 0; i < NN; i++) {
        for (int j = 0; j < NN; j++) {
            if (!cell_mask_ct(i, j)) continue;
            int len = j - i + 1;
            int k = 0;
            while ((1 << (k + 1)) <= len) k++;             // floor(log2(len))
            int ri = j + 1 - (1 << k);
            unsigned offL = (unsigned)(k * NN + i);
            unsigned offR = (unsigned)(k * NN + ri);
            t.m[cnt++] = (unsigned)(i * NN + j) | (offL << 12) | (offR << 21);
        }
    }
    return t;
}
__device__ constexpr Meta g_meta = gen_meta();

__global__ void __launch_bounds__(256)
sbc_kernel(const float* __restrict__ x,
           float* __restrict__ boundary,
           float* __restrict__ content,
           float* __restrict__ mask_out)
{
    __shared__ float Mf[RPC][7 * NN];     // sparse max tables; Mf[r][0..63] = x row
    __shared__ float ctile[RPC][NCELLS];  // content values (zero elsewhere)

    const int bd0 = blockIdx.x * RPC;     // first (b,d) row of this CTA
    const int tid = threadIdx.x;

    // Zero both content tiles (32 KB): exact zeros at unmasked cells.
    const float4 z = make_float4(0.f, 0.f, 0.f, 0.f);
    #pragma unroll
    for (int p = 0; p < 4; p++) {
        *reinterpret_cast<float4*>(&ctile[0][(p * 256 + tid) * 4]) = z;
        *reinterpret_cast<float4*>(&ctile[1][(p * 256 + tid) * 4]) = z;
    }

    // Both rows are contiguous in x: one coalesced 128-float load.
    if (tid < RPC * NN)
        Mf[tid >> 6][tid & 63] = x[(size_t)bd0 * NN + tid];
    __syncthreads();

    // Sparse max tables: Mf[r][k*64+i] = max x_r[i .. min(i+2^k-1, 63)]
    #pragma unroll
    for (int k = 1; k < 7; k++) {
        if (tid < RPC * NN) {
            const int r  = tid >> 6;
            const int ii = tid & 63;
            int o = ii + (1 << (k - 1));
            if (o > NN - 1) o = NN - 1;
            Mf[r][k * NN + ii] = fmaxf(Mf[r][(k - 1) * NN + ii], Mf[r][(k - 1) * NN + o]);
        }
        __syncthreads();
    }

    // Phase 1: content at the 1104 masked cells, both rows per meta entry.
    #pragma unroll
    for (int p = 0; p < 5; p++) {
        int idx = p * 256 + tid;
        if (idx < NMASKED) {
            const unsigned m    = g_meta.m[idx];
            const int      cell = m & 4095u;
            const int      oL   = (m >> 12) & 511u;
            const int      oR   = (m >> 21) & 511u;
            ctile[0][cell] = fmaxf(Mf[0][oL], Mf[0][oR]);
            ctile[1][cell] = fmaxf(Mf[1][oL], Mf[1][oR]);
        }
    }
    __syncthreads();

    float* bA = boundary + (size_t)bd0 * NCELLS;
    float* cA = content  + (size_t)bd0 * NCELLS;
    float* bB = bA + NCELLS;
    float* cB = cA + NCELLS;

    // j-block is pass-invariant: hoist xj for both rows.
    const int j0 = (tid & 15) * 4;
    const float4 xjA = *reinterpret_cast<const float4*>(&Mf[0][j0]);
    const float4 xjB = *reinterpret_cast<const float4*>(&Mf[1][j0]);

    // Phase 2: store stream. One mask load serves both rows.
    #pragma unroll
    for (int p = 0; p < 4; p++) {
        const int g  = p * 256 + tid;
        const int c0 = g * 4;
        const int i  = g >> 4;

        const float4 mk = *reinterpret_cast<const float4*>(&g_mask.m[c0]);
        const float xAh = 0.5f * Mf[0][i];
        const float xBh = 0.5f * Mf[1][i];
        const float4 ctA = *reinterpret_cast<const float4*>(&ctile[0][c0]);
        const float4 ctB = *reinterpret_cast<const float4*>(&ctile[1][c0]);

        float4 boA, boB, coA, coB;
        boA.x = fmaf(0.5f, xjA.x, xAh) * mk.x;
        boA.y = fmaf(0.5f, xjA.y, xAh) * mk.y;
        boA.z = fmaf(0.5f, xjA.z, xAh) * mk.z;
        boA.w = fmaf(0.5f, xjA.w, xAh) * mk.w;
        boB.x = fmaf(0.5f, xjB.x, xBh) * mk.x;
        boB.y = fmaf(0.5f, xjB.y, xBh) * mk.y;
        boB.z = fmaf(0.5f, xjB.z, xBh) * mk.z;
        boB.w = fmaf(0.5f, xjB.w, xBh) * mk.w;
        coA.x = ctA.x * mk.x;  coA.y = ctA.y * mk.y;
        coA.z = ctA.z * mk.z;  coA.w = ctA.w * mk.w;
        coB.x = ctB.x * mk.x;  coB.y = ctB.y * mk.y;
        coB.z = ctB.z * mk.z;  coB.w = ctB.w * mk.w;

        *reinterpret_cast<float4*>(bA + c0) = boA;
        *reinterpret_cast<float4*>(cA + c0) = coA;
        *reinterpret_cast<float4*>(bB + c0) = boB;
        *reinterpret_cast<float4*>(cB + c0) = coB;
    }

    // CTAs whose first row has d == 0 emit the broadcast mask slice for batch b.
    if ((bd0 & (ND - 1)) == 0) {
        float* mp = mask_out + (size_t)(bd0 >> 9) * NCELLS;
        #pragma unroll
        for (int p = 0; p < 4; p++) {
            const int c0 = (p * 256 + tid) * 4;
            *reinterpret_cast<float4*>(mp + c0) =
                *reinterpret_cast<const float4*>(&g_mask.m[c0]);
        }
    }
}

extern "C" void kernel_launch(void* const* d_in, const int* in_sizes, int n_in,
                              void* d_out, int out_size) {
    const float* x = (const float*)d_in[0];
    float* out = (float*)d_out;

    const size_t map_elems = (size_t)NB * ND * NN * NN;   // 33,554,432
    float* boundary = out;
    float* content  = out + map_elems;
    float* mask_out = out + 2 * map_elems;

    sbc_kernel<<<(NB * ND) / RPC, 256>>>(x, boundary, content, mask_out);
}

// round 6
// speedup vs baseline: 1.4571x; 1.0156x over previous
#include <cuda_runtime.h>
#include <cuda_bf16.h>
#include <cstdint>

// SparseBoundaryContent: x [16, 512, 64] f32.
// boundary(i,j) = (x[i]+x[j])/2 on masked cells, content(i,j) = max(x[i..j])
// on masked cells, 0 elsewhere.
// Output layout (flat f32): [boundary B*D*N*N][content B*D*N*N][mask B*N*N].
//
// R5: build masked tiles in SHARED (zero-fill + scatter only the 1104 masked
// cells), then bulk-store 16KB tiles to global via the TMA/async-proxy path
// (cp.async.bulk), freeing the saturated L1tex/STG pipe.

#define NB 16
#define ND 512
#define NN 64
#define NCELLS 4096          // 64*64 cells per (b,d) row
#define NMASKED 1104         // masked cells per tile (incl. diagonal)

constexpr bool cell_mask_ct(int i, int j) {
    int d = j - i;
    if (d < 0)  return false;
    if (d <= 15) return true;                              // stride-1 offsets 0..15
    if (d <= 31) return (d & 1) && !(i & 1);               // stride-2: odd 17..31, i even
    return (d >= 35) && ((d & 3) == 3) && !(i & 3);        // stride-4: 35,39,..,63, i%4==0
}

struct MaskTab { float m[NCELLS]; };
constexpr MaskTab gen_mask() {
    MaskTab t{};
    for (int i = 0; i < NN; i++)
        for (int j = 0; j < NN; j++)
            t.m[i * NN + j] = cell_mask_ct(i, j) ? 1.0f : 0.0f;
    return t;
}
__device__ constexpr MaskTab g_mask = gen_mask();

struct Meta { unsigned int m[NMASKED]; };
constexpr Meta gen_meta() {
    Meta t{};
    int cnt = 0;
    for (int i = 0; i < NN; i++) {
        for (int j = 0; j < NN; j++) {
            if (!cell_mask_ct(i, j)) continue;
            int len = j - i + 1;
            int k = 0;
            while ((1 << (k + 1)) <= len) k++;             // floor(log2(len))
            int ri = j + 1 - (1 << k);
            unsigned offL = (unsigned)(k * NN + i);
            unsigned offR = (unsigned)(k * NN + ri);
            t.m[cnt++] = (unsigned)(i * NN + j) | (offL << 12) | (offR << 21);
        }
    }
    return t;
}
__device__ constexpr Meta g_meta = gen_meta();

__device__ __forceinline__ uint32_t smem_u32(const void* p) {
    uint32_t a;
    asm("{ .reg .u64 t; cvta.to.shared.u64 t, %1; cvt.u32.u64 %0, t; }"
        : "=r"(a) : "l"(p));
    return a;
}

__global__ void __launch_bounds__(256)
sbc_kernel(const float* __restrict__ x,
           float* __restrict__ boundary,
           float* __restrict__ content,
           float* __restrict__ mask_out)
{
    __shared__ float Mf[7 * NN];                 // sparse max table; Mf[0..63] = x row
    __shared__ alignas(128) float bt[NCELLS];    // masked boundary tile (16 KB)
    __shared__ alignas(128) float ct[NCELLS];    // masked content tile  (16 KB)

    const int bd  = blockIdx.x;                  // bd = b*ND + d
    const int tid = threadIdx.x;

    // Zero-fill both tiles: unmasked cells are exact zeros.
    const float4 z = make_float4(0.f, 0.f, 0.f, 0.f);
    #pragma unroll
    for (int p = 0; p < 4; p++) {
        reinterpret_cast<float4*>(bt)[p * 256 + tid] = z;
        reinterpret_cast<float4*>(ct)[p * 256 + tid] = z;
    }

    if (tid < NN) Mf[tid] = x[(size_t)bd * NN + tid];
    __syncthreads();

    // Sparse max table: Mf[k*64+i] = max x[i .. min(i+2^k-1, 63)]
    #pragma unroll
    for (int k = 1; k < 7; k++) {
        if (tid < NN) {
            int o = tid + (1 << (k - 1));
            if (o > NN - 1) o = NN - 1;
            Mf[k * NN + tid] = fmaxf(Mf[(k - 1) * NN + tid], Mf[(k - 1) * NN + o]);
        }
        __syncthreads();
    }

    // Scatter boundary + content at the 1104 masked cells only.
    #pragma unroll
    for (int p = 0; p < 5; p++) {
        int idx = p * 256 + tid;
        if (idx < NMASKED) {
            const unsigned m    = g_meta.m[idx];
            const int      cell = m & 4095u;
            const int      i    = cell >> 6;
            const int      j    = cell & 63;
            bt[cell] = (Mf[i] + Mf[j]) * 0.5f;
            ct[cell] = fmaxf(Mf[(m >> 12) & 511u], Mf[(m >> 21) & 511u]);
        }
    }

    // Make generic-proxy smem writes visible to the async proxy, then sync.
    asm volatile("fence.proxy.async.shared::cta;" ::: "memory");
    __syncthreads();

    // Bulk-store both 16 KB tiles via the async proxy (no STG wavefronts).
    if (tid == 0) {
        const uint32_t sb = smem_u32(bt);
        const uint32_t sc = smem_u32(ct);
        float* gb = boundary + (size_t)bd * NCELLS;
        float* gc = content  + (size_t)bd * NCELLS;
        asm volatile("cp.async.bulk.global.shared::cta.bulk_group [%0], [%1], %2;"
                     :: "l"(gb), "r"(sb), "n"(NCELLS * 4) : "memory");
        asm volatile("cp.async.bulk.global.shared::cta.bulk_group [%0], [%1], %2;"
                     :: "l"(gc), "r"(sc), "n"(NCELLS * 4) : "memory");
        asm volatile("cp.async.bulk.commit_group;" ::: "memory");
    }

    // 16 CTAs (d == 0) emit the broadcast mask slice for their batch b.
    if ((bd & (ND - 1)) == 0) {
        float* mp = mask_out + (size_t)(bd >> 9) * NCELLS;
        #pragma unroll
        for (int p = 0; p < 4; p++) {
            const int c0 = (p * 256 + tid) * 4;
            *reinterpret_cast<float4*>(mp + c0) =
                *reinterpret_cast<const float4*>(&g_mask.m[c0]);
        }
    }

    // Issuing thread waits for bulk stores before CTA teardown (smem reuse safety).
    if (tid == 0)
        asm volatile("cp.async.bulk.wait_group 0;" ::: "memory");
}

extern "C" void kernel_launch(void* const* d_in, const int* in_sizes, int n_in,
                              void* d_out, int out_size) {
    const float* x = (const float*)d_in[0];
    float* out = (float*)d_out;

    const size_t map_elems = (size_t)NB * ND * NN * NN;   // 33,554,432
    float* boundary = out;
    float* content  = out + map_elems;
    float* mask_out = out + 2 * map_elems;

    sbc_kernel<<<NB * ND, 256>>>(x, boundary, content, mask_out);
}